// round 14
// baseline (speedup 1.0000x reference)
#include <cuda_runtime.h>
#include <cuda_bf16.h>
#include <cstdint>
#include <math.h>

#define T_TOT 65536
#define C_DIM 256
#define M_DIM 128
#define SHRINKV 0.0025f
#define EPSV 1e-12f

typedef unsigned long long ull;

__device__ __forceinline__ uint32_t smem_u32(const void* p) {
    uint32_t a;
    asm("{ .reg .u64 t; cvta.to.shared.u64 t, %1; cvt.u32.u64 %0, t; }" : "=r"(a) : "l"(p));
    return a;
}
#define LDMATRIX_X4(r0, r1, r2, r3, addr) \
    asm volatile("ldmatrix.sync.aligned.m8n8.x4.shared.b16 {%0,%1,%2,%3}, [%4];" \
        : "=r"(r0), "=r"(r1), "=r"(r2), "=r"(r3) : "r"(addr))
#define LDMATRIX_X4T(r0, r1, r2, r3, addr) \
    asm volatile("ldmatrix.sync.aligned.m8n8.x4.trans.shared.b16 {%0,%1,%2,%3}, [%4];" \
        : "=r"(r0), "=r"(r1), "=r"(r2), "=r"(r3) : "r"(addr))
#define MMA_BF16(acc, a, b) \
    asm("mma.sync.aligned.m16n8k16.row.col.f32.bf16.bf16.f32 " \
        "{%0,%1,%2,%3}, {%4,%5,%6,%7}, {%8,%9}, {%0,%1,%2,%3};" \
        : "+f"((acc)[0]), "+f"((acc)[1]), "+f"((acc)[2]), "+f"((acc)[3]) \
        : "r"((a)[0]), "r"((a)[1]), "r"((a)[2]), "r"((a)[3]), "r"((b)[0]), "r"((b)[1]))

__device__ __forceinline__ uint32_t bfpair(float x, float y) {
    __nv_bfloat162 p = __floats2bfloat162_rn(x, y);
    return *(uint32_t*)&p;
}
__device__ __forceinline__ float bf_lo_f(uint32_t p) {
    return __uint_as_float((p & 0xFFFFu) << 16);
}
__device__ __forceinline__ float bf_hi_f(uint32_t p) {
    return __uint_as_float(p & 0xFFFF0000u);
}
__device__ __forceinline__ void split2(float x, float y, uint32_t& hi, uint32_t& lo) {
    hi = bfpair(x, y);
    lo = bfpair(x - bf_lo_f(hi), y - bf_hi_f(hi));
}

// ---------------- scratch ----------------
__device__ float g_S[(size_t)M_DIM * T_TOT];      // exp(scores), [m][t]
__device__ float g_rowpart[512 * M_DIM];          // per-block rowsum partials
__device__ float g_l1[M_DIM];
__device__ float g_addmem[M_DIM * C_DIM];
__device__ float g_newmem[M_DIM * C_DIM];

// ---------------- K1: S[m][t] = exp(mem[m].q[t]); rowsum partials; init duty ----------------
#define QB_STR 264
__global__ __launch_bounds__(256) void k1_mma(const float* __restrict__ q,
                                              const float* __restrict__ mem) {
    extern __shared__ __nv_bfloat16 qsm[];
    __nv_bfloat16* Bh = qsm;
    __nv_bfloat16* Bl = qsm + 128 * QB_STR;
    __shared__ float rsum[128];

    int tid = threadIdx.x, lane = tid & 31, warp = tid >> 5;
    int t0 = blockIdx.x * 128;
    int m0 = (warp >> 1) * 32;
    int t0w = (warp & 1) * 64;

    // stage q tile -> bf16 hi/lo smem
    for (int i = tid * 4; i < 128 * 256; i += 1024) {
        int t = i >> 8, k = i & 255;
        float4 v = *(const float4*)&q[(size_t)(t0 + t) * C_DIM + k];
        float vv[4] = {v.x, v.y, v.z, v.w};
#pragma unroll
        for (int u = 0; u < 4; u++) {
            __nv_bfloat16 h = __float2bfloat16(vv[u]);
            Bh[t * QB_STR + k + u] = h;
            Bl[t * QB_STR + k + u] = __float2bfloat16(vv[u] - __bfloat162float(h));
        }
    }
    if (blockIdx.x == 0) {
        if (tid < M_DIM) g_l1[tid] = 0.f;
        for (int i = tid * 4; i < M_DIM * C_DIM; i += 1024)
            *(float4*)&g_addmem[i] = make_float4(0.f, 0.f, 0.f, 0.f);
    }
    if (tid < 128) rsum[tid] = 0.f;
    __syncthreads();

    uint32_t sBh = smem_u32(Bh), sBl = smem_u32(Bl);

    float acc[2][8][4];
#pragma unroll
    for (int mf = 0; mf < 2; mf++)
#pragma unroll
        for (int nf = 0; nf < 8; nf++)
#pragma unroll
            for (int u = 0; u < 4; u++) acc[mf][nf][u] = 0.f;

    int g = lane >> 2, t2 = (lane & 3) * 2;
    int lrow = (lane & 7) + ((lane >> 4) << 3);
    int lcol = (lane & 8);

    float2 pf[8];
#pragma unroll
    for (int mf = 0; mf < 2; mf++) {
        int mb = m0 + mf * 16;
        pf[mf * 4 + 0] = *(const float2*)&mem[(mb + g) * C_DIM + t2];
        pf[mf * 4 + 1] = *(const float2*)&mem[(mb + g + 8) * C_DIM + t2];
        pf[mf * 4 + 2] = *(const float2*)&mem[(mb + g) * C_DIM + t2 + 8];
        pf[mf * 4 + 3] = *(const float2*)&mem[(mb + g + 8) * C_DIM + t2 + 8];
    }

    for (int ks = 0; ks < 16; ks++) {
        int k0 = ks * 16;
        float2 f[8];
#pragma unroll
        for (int u = 0; u < 8; u++) f[u] = pf[u];
        if (ks < 15) {
            int kn = k0 + 16;
#pragma unroll
            for (int mf = 0; mf < 2; mf++) {
                int mb = m0 + mf * 16;
                pf[mf * 4 + 0] = *(const float2*)&mem[(mb + g) * C_DIM + kn + t2];
                pf[mf * 4 + 1] = *(const float2*)&mem[(mb + g + 8) * C_DIM + kn + t2];
                pf[mf * 4 + 2] = *(const float2*)&mem[(mb + g) * C_DIM + kn + t2 + 8];
                pf[mf * 4 + 3] = *(const float2*)&mem[(mb + g + 8) * C_DIM + kn + t2 + 8];
            }
        }
        uint32_t ah[2][4], al[2][4];
#pragma unroll
        for (int mf = 0; mf < 2; mf++)
#pragma unroll
            for (int u = 0; u < 4; u++)
                split2(f[mf * 4 + u].x, f[mf * 4 + u].y, ah[mf][u], al[mf][u]);

        uint32_t bh[8][2], bl[8][2];
#pragma unroll
        for (int pr = 0; pr < 4; pr++) {
            int tb = t0w + pr * 16;
            uint32_t off = (uint32_t)((tb + lrow) * QB_STR + k0 + lcol) * 2;
            LDMATRIX_X4(bh[pr * 2][0], bh[pr * 2][1], bh[pr * 2 + 1][0], bh[pr * 2 + 1][1], sBh + off);
            LDMATRIX_X4(bl[pr * 2][0], bl[pr * 2][1], bl[pr * 2 + 1][0], bl[pr * 2 + 1][1], sBl + off);
        }
#pragma unroll
        for (int mf = 0; mf < 2; mf++)
#pragma unroll
            for (int nf = 0; nf < 8; nf++) MMA_BF16(acc[mf][nf], ah[mf], bh[nf]);
#pragma unroll
        for (int mf = 0; mf < 2; mf++)
#pragma unroll
            for (int nf = 0; nf < 8; nf++) MMA_BF16(acc[mf][nf], ah[mf], bl[nf]);
#pragma unroll
        for (int mf = 0; mf < 2; mf++)
#pragma unroll
            for (int nf = 0; nf < 8; nf++) MMA_BF16(acc[mf][nf], al[mf], bh[nf]);
    }

#pragma unroll
    for (int mf = 0; mf < 2; mf++) {
        float p0 = 0.f, p1 = 0.f;
        int mr0 = m0 + mf * 16 + g;
        int mr1 = mr0 + 8;
#pragma unroll
        for (int nf = 0; nf < 8; nf++) {
            int ta = t0 + t0w + nf * 8 + t2;
            float e0 = __expf(acc[mf][nf][0]);
            float e1 = __expf(acc[mf][nf][1]);
            float e2 = __expf(acc[mf][nf][2]);
            float e3 = __expf(acc[mf][nf][3]);
            *(float2*)&g_S[(size_t)mr0 * T_TOT + ta] = make_float2(e0, e1);
            *(float2*)&g_S[(size_t)mr1 * T_TOT + ta] = make_float2(e2, e3);
            p0 += e0 + e1;
            p1 += e2 + e3;
        }
#pragma unroll
        for (int o = 1; o < 4; o <<= 1) {
            p0 += __shfl_xor_sync(0xffffffffu, p0, o);
            p1 += __shfl_xor_sync(0xffffffffu, p1, o);
        }
        if ((lane & 3) == 0) {
            atomicAdd(&rsum[mr0], p0);
            atomicAdd(&rsum[mr1], p1);
        }
    }
    __syncthreads();
    if (tid < 128) g_rowpart[blockIdx.x * 128 + tid] = rsum[tid];
}

// ---------------- K2: rowsum reduce + scan + shrink + l1 + inline sparse scatter ----------------
__global__ __launch_bounds__(256) void k2_scan(const float* __restrict__ q) {
    __shared__ float red[256];
    __shared__ float rs_sh;
    int tid = threadIdx.x, lane = tid & 31;
    int m = blockIdx.y;

    float p = g_rowpart[tid * 128 + m] + g_rowpart[(tid + 256) * 128 + m];
    red[tid] = p;
    __syncthreads();
    for (int s = 128; s > 0; s >>= 1) {
        if (tid < s) red[tid] += red[tid + s];
        __syncthreads();
    }
    if (tid == 0) rs_sh = red[0];
    __syncthreads();
    float rs = rs_sh;
    float thr = SHRINKV * rs;
    float inv = 1.0f / rs;

    size_t rowbase = (size_t)m * T_TOT;
    int tbase = blockIdx.x * 16384 + tid * 4;
#pragma unroll
    for (int j = 0; j < 16; j++) {
        int t = tbase + j * 1024;
        float4 v = *(const float4*)&g_S[rowbase + t];
        float e[4] = {v.x, v.y, v.z, v.w};
#pragma unroll
        for (int k = 0; k < 4; k++) {
            bool hit = e[k] > thr;
            float h = 0.f;
            if (hit) {
                float a = e[k] * inv;
                float d = a - SHRINKV;
                h = (d > 0.f) ? d * a / (d + EPSV) : 0.f;
                atomicAdd(&g_l1[m], h);
            }
            unsigned mask = __ballot_sync(0xffffffffu, hit);
            while (mask) {
                int src = __ffs(mask) - 1;
                mask &= mask - 1;
                float hs = __shfl_sync(0xffffffffu, h, src);
                int ts = __shfl_sync(0xffffffffu, t + k, src);
#pragma unroll
                for (int u = 0; u < 8; u++) {
                    int c = lane + u * 32;
                    atomicAdd(&g_addmem[m * C_DIM + c], hs * q[(size_t)ts * C_DIM + c]);
                }
            }
        }
    }
}

// ---------------- K4: gate + new_mem ----------------
__global__ __launch_bounds__(256) void k4_gate(const float* __restrict__ mem,
                                               const float* __restrict__ Uw,
                                               const float* __restrict__ Ub,
                                               const float* __restrict__ Ww,
                                               const float* __restrict__ Wb,
                                               float* __restrict__ nm_out) {
    __shared__ float mr[8][256], ar[8][256];
    int c = threadIdx.x;
    int m0 = blockIdx.x * 8;

    for (int i = 0; i < 8; i++) {
        int m = m0 + i;
        float invl1 = 1.0f / fmaxf(g_l1[m], EPSV);
        mr[i][c] = mem[m * C_DIM + c];
        ar[i][c] = g_addmem[m * C_DIM + c] * invl1;
    }
    __syncthreads();

    float s[8];
    float b = Ub[c] + Wb[c];
#pragma unroll
    for (int i = 0; i < 8; i++) s[i] = b;

    const float* uw = Uw + c * C_DIM;
    const float* ww = Ww + c * C_DIM;
    for (int k = 0; k < C_DIM; k += 4) {
        float4 wu4 = *(const float4*)&uw[k];
        float4 wv4 = *(const float4*)&ww[k];
        float wu[4] = {wu4.x, wu4.y, wu4.z, wu4.w};
        float wv[4] = {wv4.x, wv4.y, wv4.z, wv4.w};
#pragma unroll
        for (int u = 0; u < 4; u++)
#pragma unroll
            for (int i = 0; i < 8; i++)
                s[i] += mr[i][k + u] * wu[u] + ar[i][k + u] * wv[u];
    }
#pragma unroll
    for (int i = 0; i < 8; i++) {
        int m = m0 + i;
        float g = 1.f / (1.f + __expf(-s[i]));
        float nm = (1.f - g) * mr[i][c] + g * ar[i][c];
        g_newmem[m * C_DIM + c] = nm;
        nm_out[m * C_DIM + c] = nm;
    }
}

// ---------------- K5: persistent fused read phase (stage nm once, 4 tiles/block) ----------------
#define NMS 264
#define N_TILES 512
#define K5_BLKS 128
__global__ __launch_bounds__(256) void k5_mma(const float* __restrict__ q,
                                              float* __restrict__ out,
                                              float* __restrict__ attn) {
    extern __shared__ __nv_bfloat16 sm5[];
    __nv_bfloat16* Nh = sm5;
    __nv_bfloat16* Nl = sm5 + 128 * NMS;

    int tid = threadIdx.x, lane = tid & 31, warp = tid >> 5;

    // stage new_mem ONCE per block (read-only afterwards; no per-tile syncs)
    for (int i = tid * 2; i < 128 * 256; i += 512) {
        int m = i >> 8, c = i & 255;
        float2 v = *(const float2*)&g_newmem[i];
        uint32_t hi, lo;
        split2(v.x, v.y, hi, lo);
        *(uint32_t*)&Nh[m * NMS + c] = hi;
        *(uint32_t*)&Nl[m * NMS + c] = lo;
    }
    __syncthreads();

    uint32_t sNh = smem_u32(Nh), sNl = smem_u32(Nl);

    int g = lane >> 2, t2 = (lane & 3) * 2;
    int lrow = (lane & 7) + ((lane >> 4) << 3);
    int lcol = (lane & 8);
    int tw = warp * 16;

    for (int tile = blockIdx.x; tile < N_TILES; tile += K5_BLKS) {
        size_t T0 = (size_t)tile * 128;
        size_t rowg = T0 + tw + g;
        size_t rowg8 = rowg + 8;

        // q copy -> out[:, 0:256] (per-warp slice of the tile)
        {
            int wt0 = warp * 16;
            for (int l = lane * 4; l < 16 * 256; l += 128) {
                int t = wt0 + (l >> 8), c = l & 255;
                float4 v = *(const float4*)&q[(T0 + t) * C_DIM + c];
                *(float4*)&out[(T0 + t) * 512 + c] = v;
            }
        }

        // ==== phase 1: scores 16t x 128m, prefetch depth 2 ====
        float acc[16][4];
#pragma unroll
        for (int j = 0; j < 16; j++)
#pragma unroll
            for (int u = 0; u < 4; u++) acc[j][u] = 0.f;

        float2 pfA[2][4];
#pragma unroll
        for (int sl = 0; sl < 2; sl++) {
            int kn = sl * 16;
            pfA[sl][0] = *(const float2*)&q[rowg * C_DIM + kn + t2];
            pfA[sl][1] = *(const float2*)&q[rowg8 * C_DIM + kn + t2];
            pfA[sl][2] = *(const float2*)&q[rowg * C_DIM + kn + t2 + 8];
            pfA[sl][3] = *(const float2*)&q[rowg8 * C_DIM + kn + t2 + 8];
        }

        for (int ks = 0; ks < 16; ks++) {
            int k0 = ks * 16;
            int slot = ks & 1;
            float2 f0 = pfA[slot][0], f1 = pfA[slot][1], f2 = pfA[slot][2], f3 = pfA[slot][3];
            if (ks < 14) {
                int kn = k0 + 32;
                pfA[slot][0] = *(const float2*)&q[rowg * C_DIM + kn + t2];
                pfA[slot][1] = *(const float2*)&q[rowg8 * C_DIM + kn + t2];
                pfA[slot][2] = *(const float2*)&q[rowg * C_DIM + kn + t2 + 8];
                pfA[slot][3] = *(const float2*)&q[rowg8 * C_DIM + kn + t2 + 8];
            }
            uint32_t ah[4], al[4];
            split2(f0.x, f0.y, ah[0], al[0]);
            split2(f1.x, f1.y, ah[1], al[1]);
            split2(f2.x, f2.y, ah[2], al[2]);
            split2(f3.x, f3.y, ah[3], al[3]);

            uint32_t bh[16][2], bl[16][2];
#pragma unroll
            for (int bp = 0; bp < 8; bp++) {
                uint32_t off = (uint32_t)((16 * bp + lrow) * NMS + k0 + lcol) * 2;
                LDMATRIX_X4(bh[2 * bp][0], bh[2 * bp][1], bh[2 * bp + 1][0], bh[2 * bp + 1][1], sNh + off);
                LDMATRIX_X4(bl[2 * bp][0], bl[2 * bp][1], bl[2 * bp + 1][0], bl[2 * bp + 1][1], sNl + off);
            }
#pragma unroll
            for (int j = 0; j < 16; j++) MMA_BF16(acc[j], ah, bh[j]);
#pragma unroll
            for (int j = 0; j < 16; j++) MMA_BF16(acc[j], ah, bl[j]);
#pragma unroll
            for (int j = 0; j < 16; j++) MMA_BF16(acc[j], al, bh[j]);
        }

        // ==== softmax + shrink + l1-normalize (quad-local) ====
        {
            float mx0 = -1e30f, mx1 = -1e30f;
#pragma unroll
            for (int j = 0; j < 16; j++) {
                mx0 = fmaxf(mx0, fmaxf(acc[j][0], acc[j][1]));
                mx1 = fmaxf(mx1, fmaxf(acc[j][2], acc[j][3]));
            }
#pragma unroll
            for (int o = 1; o < 4; o <<= 1) {
                mx0 = fmaxf(mx0, __shfl_xor_sync(0xffffffffu, mx0, o));
                mx1 = fmaxf(mx1, __shfl_xor_sync(0xffffffffu, mx1, o));
            }
            float s0 = 0.f, s1 = 0.f;
#pragma unroll
            for (int j = 0; j < 16; j++) {
                acc[j][0] = __expf(acc[j][0] - mx0);
                acc[j][1] = __expf(acc[j][1] - mx0);
                acc[j][2] = __expf(acc[j][2] - mx1);
                acc[j][3] = __expf(acc[j][3] - mx1);
                s0 += acc[j][0] + acc[j][1];
                s1 += acc[j][2] + acc[j][3];
            }
#pragma unroll
            for (int o = 1; o < 4; o <<= 1) {
                s0 += __shfl_xor_sync(0xffffffffu, s0, o);
                s1 += __shfl_xor_sync(0xffffffffu, s1, o);
            }
            float i0 = 1.f / s0, i1 = 1.f / s1;
            float l10 = 0.f, l11 = 0.f;
#pragma unroll
            for (int j = 0; j < 16; j++) {
                float a0 = acc[j][0] * i0, a1 = acc[j][1] * i0;
                float a2 = acc[j][2] * i1, a3 = acc[j][3] * i1;
                float d0 = a0 - SHRINKV, d1 = a1 - SHRINKV;
                float d2 = a2 - SHRINKV, d3 = a3 - SHRINKV;
                acc[j][0] = (d0 > 0.f) ? __fdividef(d0 * a0, d0 + EPSV) : 0.f;
                acc[j][1] = (d1 > 0.f) ? __fdividef(d1 * a1, d1 + EPSV) : 0.f;
                acc[j][2] = (d2 > 0.f) ? __fdividef(d2 * a2, d2 + EPSV) : 0.f;
                acc[j][3] = (d3 > 0.f) ? __fdividef(d3 * a3, d3 + EPSV) : 0.f;
                l10 += acc[j][0] + acc[j][1];
                l11 += acc[j][2] + acc[j][3];
            }
#pragma unroll
            for (int o = 1; o < 4; o <<= 1) {
                l10 += __shfl_xor_sync(0xffffffffu, l10, o);
                l11 += __shfl_xor_sync(0xffffffffu, l11, o);
            }
            float n0 = 1.f / fmaxf(l10, EPSV), n1 = 1.f / fmaxf(l11, EPSV);
#pragma unroll
            for (int j = 0; j < 16; j++) {
                acc[j][0] *= n0; acc[j][1] *= n0;
                acc[j][2] *= n1; acc[j][3] *= n1;
                int mm = 8 * j + t2;
                *(float2*)&attn[rowg * M_DIM + mm] = make_float2(acc[j][0], acc[j][1]);
                *(float2*)&attn[rowg8 * M_DIM + mm] = make_float2(acc[j][2], acc[j][3]);
            }
        }

        // ==== h -> a-frags bf16 hi/lo ====
        uint32_t hh[8][4], hl[8][4];
#pragma unroll
        for (int s = 0; s < 8; s++) {
            split2(acc[2 * s][0], acc[2 * s][1], hh[s][0], hl[s][0]);
            split2(acc[2 * s][2], acc[2 * s][3], hh[s][1], hl[s][1]);
            split2(acc[2 * s + 1][0], acc[2 * s + 1][1], hh[s][2], hl[s][2]);
            split2(acc[2 * s + 1][2], acc[2 * s + 1][3], hh[s][3], hl[s][3]);
        }

        // ==== phase 2: add_memory 16t x 256c (two 128c passes) ====
#pragma unroll
        for (int p = 0; p < 2; p++) {
            float ac2[16][4];
#pragma unroll
            for (int j = 0; j < 16; j++)
#pragma unroll
                for (int u = 0; u < 4; u++) ac2[j][u] = 0.f;

#pragma unroll
            for (int s = 0; s < 8; s++) {
                uint32_t bh[16][2], bl[16][2];
#pragma unroll
                for (int np = 0; np < 8; np++) {
                    uint32_t off = (uint32_t)((16 * s + (lane & 15)) * NMS
                                  + p * 128 + np * 16 + ((lane >> 4) * 8)) * 2;
                    LDMATRIX_X4T(bh[2 * np][0], bh[2 * np][1], bh[2 * np + 1][0], bh[2 * np + 1][1], sNh + off);
                    LDMATRIX_X4T(bl[2 * np][0], bl[2 * np][1], bl[2 * np + 1][0], bl[2 * np + 1][1], sNl + off);
                }
#pragma unroll
                for (int j = 0; j < 16; j++) MMA_BF16(ac2[j], hh[s], bh[j]);
#pragma unroll
                for (int j = 0; j < 16; j++) MMA_BF16(ac2[j], hh[s], bl[j]);
#pragma unroll
                for (int j = 0; j < 16; j++) MMA_BF16(ac2[j], hl[s], bh[j]);
            }
#pragma unroll
            for (int nf = 0; nf < 16; nf++) {
                int c = 256 + p * 128 + nf * 8 + t2;
                *(float2*)&out[rowg * 512 + c] = make_float2(ac2[nf][0], ac2[nf][1]);
                *(float2*)&out[rowg8 * 512 + c] = make_float2(ac2[nf][2], ac2[nf][3]);
            }
        }
    }
}

// ---------------- launcher ----------------
extern "C" void kernel_launch(void* const* d_in, const int* in_sizes, int n_in,
                              void* d_out, int out_size) {
    const float* query = (const float*)d_in[0];
    const float* mem   = (const float*)d_in[1];
    const float* Uw    = (const float*)d_in[2];
    const float* Ub    = (const float*)d_in[3];
    const float* Ww    = (const float*)d_in[4];
    const float* Wb    = (const float*)d_in[5];

    float* out  = (float*)d_out;
    float* attn = out + (size_t)T_TOT * 512;
    float* nmo  = attn + (size_t)T_TOT * M_DIM;

    const int SMEM1 = 2 * 128 * QB_STR * 2;
    const int SMEM5 = 2 * 128 * NMS * 2;
    cudaFuncSetAttribute(k1_mma, cudaFuncAttributeMaxDynamicSharedMemorySize, SMEM1);
    cudaFuncSetAttribute(k5_mma, cudaFuncAttributeMaxDynamicSharedMemorySize, SMEM5);

    k1_mma<<<T_TOT / 128, 256, SMEM1>>>(query, mem);
    k2_scan<<<dim3(4, 128), 256>>>(query);
    k4_gate<<<16, 256>>>(mem, Uw, Ub, Ww, Wb, nmo);
    k5_mma<<<K5_BLKS, 256, SMEM5>>>(query, out, attn);
}

// round 15
// speedup vs baseline: 1.1071x; 1.1071x over previous
#include <cuda_runtime.h>
#include <cuda_bf16.h>
#include <cstdint>
#include <math.h>

#define T_TOT 65536
#define C_DIM 256
#define M_DIM 128
#define SHRINKV 0.0025f
#define EPSV 1e-12f

typedef unsigned long long ull;

__device__ __forceinline__ uint32_t smem_u32(const void* p) {
    uint32_t a;
    asm("{ .reg .u64 t; cvta.to.shared.u64 t, %1; cvt.u32.u64 %0, t; }" : "=r"(a) : "l"(p));
    return a;
}
#define LDMATRIX_X4(r0, r1, r2, r3, addr) \
    asm volatile("ldmatrix.sync.aligned.m8n8.x4.shared.b16 {%0,%1,%2,%3}, [%4];" \
        : "=r"(r0), "=r"(r1), "=r"(r2), "=r"(r3) : "r"(addr))
#define LDMATRIX_X4T(r0, r1, r2, r3, addr) \
    asm volatile("ldmatrix.sync.aligned.m8n8.x4.trans.shared.b16 {%0,%1,%2,%3}, [%4];" \
        : "=r"(r0), "=r"(r1), "=r"(r2), "=r"(r3) : "r"(addr))
#define MMA_BF16(acc, a, b) \
    asm("mma.sync.aligned.m16n8k16.row.col.f32.bf16.bf16.f32 " \
        "{%0,%1,%2,%3}, {%4,%5,%6,%7}, {%8,%9}, {%0,%1,%2,%3};" \
        : "+f"((acc)[0]), "+f"((acc)[1]), "+f"((acc)[2]), "+f"((acc)[3]) \
        : "r"((a)[0]), "r"((a)[1]), "r"((a)[2]), "r"((a)[3]), "r"((b)[0]), "r"((b)[1]))

__device__ __forceinline__ uint32_t bfpair(float x, float y) {
    __nv_bfloat162 p = __floats2bfloat162_rn(x, y);
    return *(uint32_t*)&p;
}
__device__ __forceinline__ float bf_lo_f(uint32_t p) {
    return __uint_as_float((p & 0xFFFFu) << 16);
}
__device__ __forceinline__ float bf_hi_f(uint32_t p) {
    return __uint_as_float(p & 0xFFFF0000u);
}
__device__ __forceinline__ void split2(float x, float y, uint32_t& hi, uint32_t& lo) {
    hi = bfpair(x, y);
    lo = bfpair(x - bf_lo_f(hi), y - bf_hi_f(hi));
}

// ---------------- scratch ----------------
__device__ float g_S[(size_t)M_DIM * T_TOT];      // exp(scores), [m][t]
__device__ float g_rowpart[512 * M_DIM];          // per-block rowsum partials
__device__ float g_l1[M_DIM];
__device__ float g_addmem[M_DIM * C_DIM];
__device__ float g_newmem[M_DIM * C_DIM];

// ---------------- K1: S[m][t] = exp(mem[m].q[t]); rowsum partials; q->out copy; init ----------------
#define QB_STR 264
__global__ __launch_bounds__(256) void k1_mma(const float* __restrict__ q,
                                              const float* __restrict__ mem,
                                              float* __restrict__ out) {
    extern __shared__ __nv_bfloat16 qsm[];
    __nv_bfloat16* Bh = qsm;
    __nv_bfloat16* Bl = qsm + 128 * QB_STR;
    __shared__ float rsum[128];

    int tid = threadIdx.x, lane = tid & 31, warp = tid >> 5;
    int t0 = blockIdx.x * 128;
    int m0 = (warp >> 1) * 32;
    int t0w = (warp & 1) * 64;

    // stage q tile -> bf16 hi/lo smem, AND copy q -> out[:, 0:256] (frees K5 of this pass)
    for (int i = tid * 4; i < 128 * 256; i += 1024) {
        int t = i >> 8, k = i & 255;
        float4 v = *(const float4*)&q[(size_t)(t0 + t) * C_DIM + k];
        *(float4*)&out[(size_t)(t0 + t) * 512 + k] = v;
        float vv[4] = {v.x, v.y, v.z, v.w};
#pragma unroll
        for (int u = 0; u < 4; u++) {
            __nv_bfloat16 h = __float2bfloat16(vv[u]);
            Bh[t * QB_STR + k + u] = h;
            Bl[t * QB_STR + k + u] = __float2bfloat16(vv[u] - __bfloat162float(h));
        }
    }
    if (blockIdx.x == 0) {
        if (tid < M_DIM) g_l1[tid] = 0.f;
        for (int i = tid * 4; i < M_DIM * C_DIM; i += 1024)
            *(float4*)&g_addmem[i] = make_float4(0.f, 0.f, 0.f, 0.f);
    }
    if (tid < 128) rsum[tid] = 0.f;
    __syncthreads();

    uint32_t sBh = smem_u32(Bh), sBl = smem_u32(Bl);

    float acc[2][8][4];
#pragma unroll
    for (int mf = 0; mf < 2; mf++)
#pragma unroll
        for (int nf = 0; nf < 8; nf++)
#pragma unroll
            for (int u = 0; u < 4; u++) acc[mf][nf][u] = 0.f;

    int g = lane >> 2, t2 = (lane & 3) * 2;
    int lrow = (lane & 7) + ((lane >> 4) << 3);
    int lcol = (lane & 8);

    float2 pf[8];
#pragma unroll
    for (int mf = 0; mf < 2; mf++) {
        int mb = m0 + mf * 16;
        pf[mf * 4 + 0] = *(const float2*)&mem[(mb + g) * C_DIM + t2];
        pf[mf * 4 + 1] = *(const float2*)&mem[(mb + g + 8) * C_DIM + t2];
        pf[mf * 4 + 2] = *(const float2*)&mem[(mb + g) * C_DIM + t2 + 8];
        pf[mf * 4 + 3] = *(const float2*)&mem[(mb + g + 8) * C_DIM + t2 + 8];
    }

    for (int ks = 0; ks < 16; ks++) {
        int k0 = ks * 16;
        float2 f[8];
#pragma unroll
        for (int u = 0; u < 8; u++) f[u] = pf[u];
        if (ks < 15) {
            int kn = k0 + 16;
#pragma unroll
            for (int mf = 0; mf < 2; mf++) {
                int mb = m0 + mf * 16;
                pf[mf * 4 + 0] = *(const float2*)&mem[(mb + g) * C_DIM + kn + t2];
                pf[mf * 4 + 1] = *(const float2*)&mem[(mb + g + 8) * C_DIM + kn + t2];
                pf[mf * 4 + 2] = *(const float2*)&mem[(mb + g) * C_DIM + kn + t2 + 8];
                pf[mf * 4 + 3] = *(const float2*)&mem[(mb + g + 8) * C_DIM + kn + t2 + 8];
            }
        }
        uint32_t ah[2][4], al[2][4];
#pragma unroll
        for (int mf = 0; mf < 2; mf++)
#pragma unroll
            for (int u = 0; u < 4; u++)
                split2(f[mf * 4 + u].x, f[mf * 4 + u].y, ah[mf][u], al[mf][u]);

        uint32_t bh[8][2], bl[8][2];
#pragma unroll
        for (int pr = 0; pr < 4; pr++) {
            int tb = t0w + pr * 16;
            uint32_t off = (uint32_t)((tb + lrow) * QB_STR + k0 + lcol) * 2;
            LDMATRIX_X4(bh[pr * 2][0], bh[pr * 2][1], bh[pr * 2 + 1][0], bh[pr * 2 + 1][1], sBh + off);
            LDMATRIX_X4(bl[pr * 2][0], bl[pr * 2][1], bl[pr * 2 + 1][0], bl[pr * 2 + 1][1], sBl + off);
        }
#pragma unroll
        for (int mf = 0; mf < 2; mf++)
#pragma unroll
            for (int nf = 0; nf < 8; nf++) MMA_BF16(acc[mf][nf], ah[mf], bh[nf]);
#pragma unroll
        for (int mf = 0; mf < 2; mf++)
#pragma unroll
            for (int nf = 0; nf < 8; nf++) MMA_BF16(acc[mf][nf], ah[mf], bl[nf]);
#pragma unroll
        for (int mf = 0; mf < 2; mf++)
#pragma unroll
            for (int nf = 0; nf < 8; nf++) MMA_BF16(acc[mf][nf], al[mf], bh[nf]);
    }

#pragma unroll
    for (int mf = 0; mf < 2; mf++) {
        float p0 = 0.f, p1 = 0.f;
        int mr0 = m0 + mf * 16 + g;
        int mr1 = mr0 + 8;
#pragma unroll
        for (int nf = 0; nf < 8; nf++) {
            int ta = t0 + t0w + nf * 8 + t2;
            float e0 = __expf(acc[mf][nf][0]);
            float e1 = __expf(acc[mf][nf][1]);
            float e2 = __expf(acc[mf][nf][2]);
            float e3 = __expf(acc[mf][nf][3]);
            *(float2*)&g_S[(size_t)mr0 * T_TOT + ta] = make_float2(e0, e1);
            *(float2*)&g_S[(size_t)mr1 * T_TOT + ta] = make_float2(e2, e3);
            p0 += e0 + e1;
            p1 += e2 + e3;
        }
#pragma unroll
        for (int o = 1; o < 4; o <<= 1) {
            p0 += __shfl_xor_sync(0xffffffffu, p0, o);
            p1 += __shfl_xor_sync(0xffffffffu, p1, o);
        }
        if ((lane & 3) == 0) {
            atomicAdd(&rsum[mr0], p0);
            atomicAdd(&rsum[mr1], p1);
        }
    }
    __syncthreads();
    if (tid < 128) g_rowpart[blockIdx.x * 128 + tid] = rsum[tid];
}

// ---------------- K2: rowsum reduce + scan + shrink + l1 + inline sparse scatter ----------------
__global__ __launch_bounds__(256) void k2_scan(const float* __restrict__ q) {
    __shared__ float red[256];
    __shared__ float rs_sh;
    int tid = threadIdx.x, lane = tid & 31;
    int m = blockIdx.y;

    float p = g_rowpart[tid * 128 + m] + g_rowpart[(tid + 256) * 128 + m];
    red[tid] = p;
    __syncthreads();
    for (int s = 128; s > 0; s >>= 1) {
        if (tid < s) red[tid] += red[tid + s];
        __syncthreads();
    }
    if (tid == 0) rs_sh = red[0];
    __syncthreads();
    float rs = rs_sh;
    float thr = SHRINKV * rs;
    float inv = 1.0f / rs;

    size_t rowbase = (size_t)m * T_TOT;
    int tbase = blockIdx.x * 16384 + tid * 4;
#pragma unroll
    for (int j = 0; j < 16; j++) {
        int t = tbase + j * 1024;
        float4 v = *(const float4*)&g_S[rowbase + t];
        float e[4] = {v.x, v.y, v.z, v.w};
#pragma unroll
        for (int k = 0; k < 4; k++) {
            bool hit = e[k] > thr;
            float h = 0.f;
            if (hit) {
                float a = e[k] * inv;
                float d = a - SHRINKV;
                h = (d > 0.f) ? d * a / (d + EPSV) : 0.f;
                atomicAdd(&g_l1[m], h);
            }
            unsigned mask = __ballot_sync(0xffffffffu, hit);
            while (mask) {
                int src = __ffs(mask) - 1;
                mask &= mask - 1;
                float hs = __shfl_sync(0xffffffffu, h, src);
                int ts = __shfl_sync(0xffffffffu, t + k, src);
#pragma unroll
                for (int u = 0; u < 8; u++) {
                    int c = lane + u * 32;
                    atomicAdd(&g_addmem[m * C_DIM + c], hs * q[(size_t)ts * C_DIM + c]);
                }
            }
        }
    }
}

// ---------------- K4: gate + new_mem ----------------
__global__ __launch_bounds__(256) void k4_gate(const float* __restrict__ mem,
                                               const float* __restrict__ Uw,
                                               const float* __restrict__ Ub,
                                               const float* __restrict__ Ww,
                                               const float* __restrict__ Wb,
                                               float* __restrict__ nm_out) {
    __shared__ float mr[8][256], ar[8][256];
    int c = threadIdx.x;
    int m0 = blockIdx.x * 8;

    for (int i = 0; i < 8; i++) {
        int m = m0 + i;
        float invl1 = 1.0f / fmaxf(g_l1[m], EPSV);
        mr[i][c] = mem[m * C_DIM + c];
        ar[i][c] = g_addmem[m * C_DIM + c] * invl1;
    }
    __syncthreads();

    float s[8];
    float b = Ub[c] + Wb[c];
#pragma unroll
    for (int i = 0; i < 8; i++) s[i] = b;

    const float* uw = Uw + c * C_DIM;
    const float* ww = Ww + c * C_DIM;
    for (int k = 0; k < C_DIM; k += 4) {
        float4 wu4 = *(const float4*)&uw[k];
        float4 wv4 = *(const float4*)&ww[k];
        float wu[4] = {wu4.x, wu4.y, wu4.z, wu4.w};
        float wv[4] = {wv4.x, wv4.y, wv4.z, wv4.w};
#pragma unroll
        for (int u = 0; u < 4; u++)
#pragma unroll
            for (int i = 0; i < 8; i++)
                s[i] += mr[i][k + u] * wu[u] + ar[i][k + u] * wv[u];
    }
#pragma unroll
    for (int i = 0; i < 8; i++) {
        int m = m0 + i;
        float g = 1.f / (1.f + __expf(-s[i]));
        float nm = (1.f - g) * mr[i][c] + g * ar[i][c];
        g_newmem[m * C_DIM + c] = nm;
        nm_out[m * C_DIM + c] = nm;
    }
}

// ---------------- K5: fused read phase via mma.sync (R12 proven shape, q-copy removed) ----------------
#define NMS 264
__global__ __launch_bounds__(256) void k5_mma(const float* __restrict__ q,
                                              float* __restrict__ out,
                                              float* __restrict__ attn) {
    extern __shared__ __nv_bfloat16 sm5[];
    __nv_bfloat16* Nh = sm5;
    __nv_bfloat16* Nl = sm5 + 128 * NMS;

    int tid = threadIdx.x, lane = tid & 31, warp = tid >> 5;
    size_t T0 = (size_t)blockIdx.x * 128;

    for (int i = tid * 2; i < 128 * 256; i += 512) {
        int m = i >> 8, c = i & 255;
        float2 v = *(const float2*)&g_newmem[i];
        uint32_t hi, lo;
        split2(v.x, v.y, hi, lo);
        *(uint32_t*)&Nh[m * NMS + c] = hi;
        *(uint32_t*)&Nl[m * NMS + c] = lo;
    }
    __syncthreads();

    uint32_t sNh = smem_u32(Nh), sNl = smem_u32(Nl);

    int g = lane >> 2, t2 = (lane & 3) * 2;
    int lrow = (lane & 7) + ((lane >> 4) << 3);
    int lcol = (lane & 8);
    int tw = warp * 16;
    size_t rowg = T0 + tw + g;
    size_t rowg8 = rowg + 8;

    // ==== phase 1: scores 16t x 128m ====
    float acc[16][4];
#pragma unroll
    for (int j = 0; j < 16; j++)
#pragma unroll
        for (int u = 0; u < 4; u++) acc[j][u] = 0.f;

    float2 pf0 = *(const float2*)&q[rowg * C_DIM + t2];
    float2 pf1 = *(const float2*)&q[rowg8 * C_DIM + t2];
    float2 pf2 = *(const float2*)&q[rowg * C_DIM + t2 + 8];
    float2 pf3 = *(const float2*)&q[rowg8 * C_DIM + t2 + 8];

    for (int ks = 0; ks < 16; ks++) {
        int k0 = ks * 16;
        float2 f0 = pf0, f1 = pf1, f2 = pf2, f3 = pf3;
        if (ks < 15) {
            int kn = k0 + 16;
            pf0 = *(const float2*)&q[rowg * C_DIM + kn + t2];
            pf1 = *(const float2*)&q[rowg8 * C_DIM + kn + t2];
            pf2 = *(const float2*)&q[rowg * C_DIM + kn + t2 + 8];
            pf3 = *(const float2*)&q[rowg8 * C_DIM + kn + t2 + 8];
        }
        uint32_t ah[4], al[4];
        split2(f0.x, f0.y, ah[0], al[0]);
        split2(f1.x, f1.y, ah[1], al[1]);
        split2(f2.x, f2.y, ah[2], al[2]);
        split2(f3.x, f3.y, ah[3], al[3]);

        uint32_t bh[16][2], bl[16][2];
#pragma unroll
        for (int bp = 0; bp < 8; bp++) {
            uint32_t off = (uint32_t)((16 * bp + lrow) * NMS + k0 + lcol) * 2;
            LDMATRIX_X4(bh[2 * bp][0], bh[2 * bp][1], bh[2 * bp + 1][0], bh[2 * bp + 1][1], sNh + off);
            LDMATRIX_X4(bl[2 * bp][0], bl[2 * bp][1], bl[2 * bp + 1][0], bl[2 * bp + 1][1], sNl + off);
        }
#pragma unroll
        for (int j = 0; j < 16; j++) MMA_BF16(acc[j], ah, bh[j]);
#pragma unroll
        for (int j = 0; j < 16; j++) MMA_BF16(acc[j], ah, bl[j]);
#pragma unroll
        for (int j = 0; j < 16; j++) MMA_BF16(acc[j], al, bh[j]);
    }

    // ==== softmax + shrink + l1-normalize (quad-local) ====
    {
        float mx0 = -1e30f, mx1 = -1e30f;
#pragma unroll
        for (int j = 0; j < 16; j++) {
            mx0 = fmaxf(mx0, fmaxf(acc[j][0], acc[j][1]));
            mx1 = fmaxf(mx1, fmaxf(acc[j][2], acc[j][3]));
        }
#pragma unroll
        for (int o = 1; o < 4; o <<= 1) {
            mx0 = fmaxf(mx0, __shfl_xor_sync(0xffffffffu, mx0, o));
            mx1 = fmaxf(mx1, __shfl_xor_sync(0xffffffffu, mx1, o));
        }
        float s0 = 0.f, s1 = 0.f;
#pragma unroll
        for (int j = 0; j < 16; j++) {
            acc[j][0] = __expf(acc[j][0] - mx0);
            acc[j][1] = __expf(acc[j][1] - mx0);
            acc[j][2] = __expf(acc[j][2] - mx1);
            acc[j][3] = __expf(acc[j][3] - mx1);
            s0 += acc[j][0] + acc[j][1];
            s1 += acc[j][2] + acc[j][3];
        }
#pragma unroll
        for (int o = 1; o < 4; o <<= 1) {
            s0 += __shfl_xor_sync(0xffffffffu, s0, o);
            s1 += __shfl_xor_sync(0xffffffffu, s1, o);
        }
        float i0 = 1.f / s0, i1 = 1.f / s1;
        float l10 = 0.f, l11 = 0.f;
#pragma unroll
        for (int j = 0; j < 16; j++) {
            float a0 = acc[j][0] * i0, a1 = acc[j][1] * i0;
            float a2 = acc[j][2] * i1, a3 = acc[j][3] * i1;
            float d0 = a0 - SHRINKV, d1 = a1 - SHRINKV;
            float d2 = a2 - SHRINKV, d3 = a3 - SHRINKV;
            acc[j][0] = (d0 > 0.f) ? __fdividef(d0 * a0, d0 + EPSV) : 0.f;
            acc[j][1] = (d1 > 0.f) ? __fdividef(d1 * a1, d1 + EPSV) : 0.f;
            acc[j][2] = (d2 > 0.f) ? __fdividef(d2 * a2, d2 + EPSV) : 0.f;
            acc[j][3] = (d3 > 0.f) ? __fdividef(d3 * a3, d3 + EPSV) : 0.f;
            l10 += acc[j][0] + acc[j][1];
            l11 += acc[j][2] + acc[j][3];
        }
#pragma unroll
        for (int o = 1; o < 4; o <<= 1) {
            l10 += __shfl_xor_sync(0xffffffffu, l10, o);
            l11 += __shfl_xor_sync(0xffffffffu, l11, o);
        }
        float n0 = 1.f / fmaxf(l10, EPSV), n1 = 1.f / fmaxf(l11, EPSV);
#pragma unroll
        for (int j = 0; j < 16; j++) {
            acc[j][0] *= n0; acc[j][1] *= n0;
            acc[j][2] *= n1; acc[j][3] *= n1;
            int mm = 8 * j + t2;
            *(float2*)&attn[rowg * M_DIM + mm] = make_float2(acc[j][0], acc[j][1]);
            *(float2*)&attn[rowg8 * M_DIM + mm] = make_float2(acc[j][2], acc[j][3]);
        }
    }

    // ==== h -> a-frags bf16 hi/lo ====
    uint32_t hh[8][4], hl[8][4];
#pragma unroll
    for (int s = 0; s < 8; s++) {
        split2(acc[2 * s][0], acc[2 * s][1], hh[s][0], hl[s][0]);
        split2(acc[2 * s][2], acc[2 * s][3], hh[s][1], hl[s][1]);
        split2(acc[2 * s + 1][0], acc[2 * s + 1][1], hh[s][2], hl[s][2]);
        split2(acc[2 * s + 1][2], acc[2 * s + 1][3], hh[s][3], hl[s][3]);
    }

    // ==== phase 2: add_memory 16t x 256c (two 128c passes) ====
#pragma unroll
    for (int p = 0; p < 2; p++) {
        float ac2[16][4];
#pragma unroll
        for (int j = 0; j < 16; j++)
#pragma unroll
            for (int u = 0; u < 4; u++) ac2[j][u] = 0.f;

#pragma unroll
        for (int s = 0; s < 8; s++) {
            uint32_t bh[16][2], bl[16][2];
#pragma unroll
            for (int np = 0; np < 8; np++) {
                uint32_t off = (uint32_t)((16 * s + (lane & 15)) * NMS
                              + p * 128 + np * 16 + ((lane >> 4) * 8)) * 2;
                LDMATRIX_X4T(bh[2 * np][0], bh[2 * np][1], bh[2 * np + 1][0], bh[2 * np + 1][1], sNh + off);
                LDMATRIX_X4T(bl[2 * np][0], bl[2 * np][1], bl[2 * np + 1][0], bl[2 * np + 1][1], sNl + off);
            }
#pragma unroll
            for (int j = 0; j < 16; j++) MMA_BF16(ac2[j], hh[s], bh[j]);
#pragma unroll
            for (int j = 0; j < 16; j++) MMA_BF16(ac2[j], hh[s], bl[j]);
#pragma unroll
            for (int j = 0; j < 16; j++) MMA_BF16(ac2[j], hl[s], bh[j]);
        }
#pragma unroll
        for (int nf = 0; nf < 16; nf++) {
            int c = 256 + p * 128 + nf * 8 + t2;
            *(float2*)&out[rowg * 512 + c] = make_float2(ac2[nf][0], ac2[nf][1]);
            *(float2*)&out[rowg8 * 512 + c] = make_float2(ac2[nf][2], ac2[nf][3]);
        }
    }
}

// ---------------- launcher ----------------
extern "C" void kernel_launch(void* const* d_in, const int* in_sizes, int n_in,
                              void* d_out, int out_size) {
    const float* query = (const float*)d_in[0];
    const float* mem   = (const float*)d_in[1];
    const float* Uw    = (const float*)d_in[2];
    const float* Ub    = (const float*)d_in[3];
    const float* Ww    = (const float*)d_in[4];
    const float* Wb    = (const float*)d_in[5];

    float* out  = (float*)d_out;
    float* attn = out + (size_t)T_TOT * 512;
    float* nmo  = attn + (size_t)T_TOT * M_DIM;

    const int SMEM1 = 2 * 128 * QB_STR * 2;
    const int SMEM5 = 2 * 128 * NMS * 2;
    cudaFuncSetAttribute(k1_mma, cudaFuncAttributeMaxDynamicSharedMemorySize, SMEM1);
    cudaFuncSetAttribute(k5_mma, cudaFuncAttributeMaxDynamicSharedMemorySize, SMEM5);

    k1_mma<<<T_TOT / 128, 256, SMEM1>>>(query, mem, out);
    k2_scan<<<dim3(4, 128), 256>>>(query);
    k4_gate<<<16, 256>>>(mem, Uw, Ub, Ww, Wb, nmo);
    k5_mma<<<T_TOT / 128, 256, SMEM5>>>(query, out, attn);
}